// round 15
// baseline (speedup 1.0000x reference)
#include <cuda_runtime.h>
#include <cuda_fp16.h>
#include <cstdint>

// ---------------------------------------------------------------------------
// TimeMix collapses to: out = (sigmoid(xr @ Wr^T) * (xv @ Wv^T or wkv@t0)) @ Wo^T
// For t>0 padded state is zero so wkv == v; the 4 t==0 rows use g_wkv0
// (fp32 dot products from raw inputs), selected in MODE1's epilogue.
// Engine: legacy mma.sync fp16 k16 (tcgen05 unusable: compute_103 target).
// R14: BK=32 + 5-stage cp.async (prefetch distance 4) to close the ~41%
//      tensor-pipe idle from memory-wait; t0 decoupled from the GEMM chain.
// ---------------------------------------------------------------------------

namespace {
constexpr int  BDIM = 4;
constexpr int  TDIM = 2048;
constexpr int  CDIM = 2048;
constexpr long MDIM = (long)BDIM * TDIM;   // 8192
constexpr int  KDIM = CDIM;
constexpr int  NDIM = CDIM;

constexpr int BM = 128, BN = 128, BK = 32;
constexpr int NTHREADS = 128;
constexpr int LSTR_H = 40;                          // padded row stride (halves) = 80B
constexpr int MAT_HALFS   = BM * LSTR_H;            // 5120
constexpr int MAT_BYTES   = MAT_HALFS * 2;          // 10240
constexpr int STAGE_HALFS = 2 * MAT_HALFS;          // A + B
constexpr int STAGE_BYTES = STAGE_HALFS * 2;        // 20480
constexpr int NSTAGE = 5;
constexpr int DYN_SMEM = NSTAGE * STAGE_BYTES;      // 102400
constexpr int NKT = KDIM / BK;                      // 64
}

// Scratch (static device arrays — no cudaMalloc anywhere)
__device__ __half g_xv[MDIM * KDIM];
__device__ __half g_xr[MDIM * KDIM];
__device__ __half g_rv[MDIM * NDIM];
__device__ __half g_wv[(long)NDIM * KDIM];
__device__ __half g_wr[(long)NDIM * KDIM];
__device__ __half g_wo[(long)NDIM * KDIM];
__device__ float  g_v [MDIM * NDIM];
__device__ float  g_wkv0[(long)BDIM * NDIM];        // wkv for the 4 t=0 rows

__device__ __forceinline__ void cp16(uint32_t s, const void* g) {
    asm volatile("cp.async.cg.shared.global [%0], [%1], 16;" :: "r"(s), "l"(g));
}

// ---- convert the three live weight matrices to fp16 (RN)
__global__ void prep_w_kernel(const float* __restrict__ wv,
                              const float* __restrict__ wr,
                              const float* __restrict__ wo) {
    long i = ((long)blockIdx.x * blockDim.x + threadIdx.x) * 4;
    float4 a = *(const float4*)(wv + i);
    float4 b = *(const float4*)(wr + i);
    float4 c = *(const float4*)(wo + i);
    __half2* pv = reinterpret_cast<__half2*>(g_wv + i);
    __half2* pr = reinterpret_cast<__half2*>(g_wr + i);
    __half2* po = reinterpret_cast<__half2*>(g_wo + i);
    pv[0] = __floats2half2_rn(a.x, a.y); pv[1] = __floats2half2_rn(a.z, a.w);
    pr[0] = __floats2half2_rn(b.x, b.y); pr[1] = __floats2half2_rn(b.z, b.w);
    po[0] = __floats2half2_rn(c.x, c.y); po[1] = __floats2half2_rn(c.z, c.w);
}

// ---- token-mix (fp32) + fp16 conversion for the two GEMM A-operands
__global__ void prep_x_kernel(const float* __restrict__ x,
                              const float* __restrict__ tmv,
                              const float* __restrict__ tmr,
                              const float* __restrict__ xxp) {
    long i = ((long)blockIdx.x * blockDim.x + threadIdx.x) * 4;
    int  c = (int)(i & (CDIM - 1));
    float4 xv = *(const float4*)(x   + i);
    float4 mv = *(const float4*)(tmv + c);
    float4 mr = *(const float4*)(tmr + c);
    float4 xc = *(const float4*)(xxp + c);
    float vx = xv.x * mv.x + (1.f - mv.x) * xc.x;
    float vy = xv.y * mv.y + (1.f - mv.y) * xc.y;
    float vz = xv.z * mv.z + (1.f - mv.z) * xc.z;
    float vw = xv.w * mv.w + (1.f - mv.w) * xc.w;
    float rx = xv.x * mr.x + (1.f - mr.x) * xc.x;
    float ry = xv.y * mr.y + (1.f - mr.y) * xc.y;
    float rz = xv.z * mr.z + (1.f - mr.z) * xc.z;
    float rw = xv.w * mr.w + (1.f - mr.w) * xc.w;
    __half2* pv = reinterpret_cast<__half2*>(g_xv + i);
    __half2* pr = reinterpret_cast<__half2*>(g_xr + i);
    pv[0] = __floats2half2_rn(vx, vy); pv[1] = __floats2half2_rn(vz, vw);
    pr[0] = __floats2half2_rn(rx, ry); pr[1] = __floats2half2_rn(rz, rw);
}

// ---- t==0 rows: k and v dot products (fp32) from raw inputs -> wkv -> g_wkv0.
// Runs before the GEMMs; MODE1's epilogue selects it for rows m % TDIM == 0.
__global__ void t0_wkv_kernel(const float* __restrict__ x,
                              const float* __restrict__ tf,
                              const float* __restrict__ tmk,
                              const float* __restrict__ tmv,
                              const float* __restrict__ xxp,
                              const float* __restrict__ aa,
                              const float* __restrict__ bb,
                              const float* __restrict__ pp,
                              const float* __restrict__ wk,
                              const float* __restrict__ wv) {
    const int b    = blockIdx.y;
    const int o    = blockIdx.x * 8 + (threadIdx.x >> 5);
    const int lane = threadIdx.x & 31;
    const float* xrow = x  + (long)b * TDIM * CDIM;  // x[b][0][:]
    const float* wkr  = wk + (long)o * CDIM;
    const float* wvr  = wv + (long)o * CDIM;
    float sk = 0.f, sv = 0.f;
    for (int c = lane; c < CDIM; c += 32) {
        float xc = xrow[c], mx = xxp[c];
        float mk = tmk[c], mv = tmv[c];
        sk += (xc * mk + (1.f - mk) * mx) * wkr[c];
        sv += (xc * mv + (1.f - mv) * mx) * wvr[c];
    }
    #pragma unroll
    for (int off = 16; off; off >>= 1) {
        sk += __shfl_xor_sync(0xffffffffu, sk, off);
        sv += __shfl_xor_sync(0xffffffffu, sv, off);
    }
    if (lane == 0) {
        float ww = tf[o] + sk;
        float p  = pp[o];
        float qq = fmaxf(p, ww);
        float e1 = expf(p  - qq);
        float e2 = expf(ww - qq);
        g_wkv0[(long)b * NDIM + o] = (e1 * aa[o] + e2 * sv) / (e1 * bb[o] + e2);
    }
}

// ---- fp16 mma.sync GEMM:  C[M,N] = A[M,K] @ W[N,K]^T, CTA 128x128, 4 warps,
//      warp tile 64x64, BK=32 (2 x k16 steps), 5-stage cp.async (distance 4),
//      register-fragment double buffering.
// MODE 0: g_v  = g_xv @ g_wv^T                      (fp32 out)
// MODE 1: g_rv = half( sigmoid(g_xr @ g_wr^T) * v ) (v from g_v / g_wkv0)
// MODE 2: out  = g_rv @ g_wo^T                      (fp32 out)
template<int MODE>
__global__ void __launch_bounds__(NTHREADS, 2)
gemm_f16(float* __restrict__ Cout) {
    const __half* __restrict__ A = (MODE == 0) ? g_xv : (MODE == 1) ? g_xr : g_rv;
    const __half* __restrict__ W = (MODE == 0) ? g_wv : (MODE == 1) ? g_wr : g_wo;

    extern __shared__ __half smh[];   // [5 stages][A 128x40h | B 128x40h]

    const int tid  = threadIdx.x;
    const int lane = tid & 31;
    const int warp = tid >> 5;
    const int wm = warp & 1;          // 2 warps over M (64 rows each)
    const int wn = warp >> 1;         // 2 warps over N (64 cols each)
    const int g  = lane >> 2;
    const int t  = lane & 3;
    const long bm = (long)blockIdx.y * BM;
    const long bn = (long)blockIdx.x * BN;

    float acc[4][8][4];
    #pragma unroll
    for (int i = 0; i < 4; i++)
        #pragma unroll
        for (int j = 0; j < 8; j++)
            #pragma unroll
            for (int k = 0; k < 4; k++) acc[i][j][k] = 0.f;

    const uint32_t sbase = (uint32_t)__cvta_generic_to_shared(smh);

    // cp.async: per stage A = 128 rows x 4 chunks(16B) = 512 -> 4/thread; B same.
    const int srow = tid >> 2;            // 0..31
    const int schk = (tid & 3) * 8;       // half offset of 16B chunk
    const __half* gA = A + (bm + srow) * (long)KDIM + schk;
    const __half* gB = W + (bn + srow) * (long)KDIM + schk;
    const uint32_t dOff = (uint32_t)(srow * LSTR_H + schk) * 2u;

    #define LOAD_STAGE(s, kt) do {                                               \
        uint32_t _a = sbase + (uint32_t)(s) * STAGE_BYTES + dOff;                \
        uint32_t _b = _a + (uint32_t)MAT_BYTES;                                  \
        int _k = (kt) * BK;                                                      \
        _Pragma("unroll")                                                        \
        for (int _i = 0; _i < 4; _i++) {                                         \
            cp16(_a + (uint32_t)(_i * 32 * LSTR_H * 2), gA + (long)(_i * 32) * KDIM + _k); \
            cp16(_b + (uint32_t)(_i * 32 * LSTR_H * 2), gB + (long)(_i * 32) * KDIM + _k); \
        }                                                                        \
        asm volatile("cp.async.commit_group;");                                  \
    } while (0)

    // Fragment load for one k16 step (ks in {0,1}) into buffers fa/fb
    #define LOAD_FRAGS(fa, fb, As_, Bs_, ks) do {                                \
        _Pragma("unroll")                                                        \
        for (int _im = 0; _im < 4; _im++) {                                      \
            const __half* _p = (As_) + (wm * 64 + _im * 16 + g) * LSTR_H + (ks) * 16 + 2 * t; \
            (fa)[_im][0] = *(const uint32_t*)(_p);                               \
            (fa)[_im][1] = *(const uint32_t*)(_p + 8 * LSTR_H);                  \
            (fa)[_im][2] = *(const uint32_t*)(_p + 8);                           \
            (fa)[_im][3] = *(const uint32_t*)(_p + 8 * LSTR_H + 8);              \
        }                                                                        \
        _Pragma("unroll")                                                        \
        for (int _in = 0; _in < 8; _in++) {                                      \
            const __half* _p = (Bs_) + (wn * 64 + _in * 8 + g) * LSTR_H + (ks) * 16 + 2 * t; \
            (fb)[_in][0] = *(const uint32_t*)(_p);                               \
            (fb)[_in][1] = *(const uint32_t*)(_p + 8);                           \
        }                                                                        \
    } while (0)

    LOAD_STAGE(0, 0);
    LOAD_STAGE(1, 1);
    LOAD_STAGE(2, 2);
    LOAD_STAGE(3, 3);

    uint32_t a[2][4][4], b[2][8][2];

    for (int kt = 0; kt < NKT; ++kt) {
        asm volatile("cp.async.wait_group 3;" ::: "memory");
        __syncthreads();
        const __half* As_ = smh + (kt % NSTAGE) * STAGE_HALFS;
        const __half* Bs_ = As_ + MAT_HALFS;
        LOAD_FRAGS(a[0], b[0], As_, Bs_, 0);          // prime ks=0 fragments
        const int jt = kt + 4;
        if (jt < NKT) { LOAD_STAGE(jt % NSTAGE, jt); }
        else          { asm volatile("cp.async.commit_group;"); }
        #pragma unroll
        for (int ks = 0; ks < 2; ks++) {
            const int cur = ks & 1, nxt = cur ^ 1;
            if (ks < 1) LOAD_FRAGS(a[nxt], b[nxt], As_, Bs_, ks + 1);
            #pragma unroll
            for (int im = 0; im < 4; im++)
                #pragma unroll
                for (int in = 0; in < 8; in++)
                    asm volatile(
                        "mma.sync.aligned.m16n8k16.row.col.f32.f16.f16.f32 "
                        "{%0,%1,%2,%3}, {%4,%5,%6,%7}, {%8,%9}, {%0,%1,%2,%3};"
                        : "+f"(acc[im][in][0]), "+f"(acc[im][in][1]),
                          "+f"(acc[im][in][2]), "+f"(acc[im][in][3])
                        : "r"(a[cur][im][0]), "r"(a[cur][im][1]),
                          "r"(a[cur][im][2]), "r"(a[cur][im][3]),
                          "r"(b[cur][in][0]), "r"(b[cur][in][1]));
        }
    }
    #undef LOAD_STAGE
    #undef LOAD_FRAGS

    // Epilogue: c0,c1 = (row m0, cols n0,n0+1); c2,c3 = row m0+8.
    #pragma unroll
    for (int im = 0; im < 4; im++) {
        const long m0 = bm + wm * 64 + im * 16 + g;
        const bool t0row = (MODE == 1) && ((m0 & (TDIM - 1)) == 0);
        #pragma unroll
        for (int in = 0; in < 8; in++) {
            const long n0 = bn + wn * 64 + in * 8 + t * 2;
            const long i0 = m0 * NDIM + n0;
            const long i1 = i0 + 8L * NDIM;
            float c0 = acc[im][in][0], c1 = acc[im][in][1];
            float c2 = acc[im][in][2], c3 = acc[im][in][3];
            if (MODE == 0) {
                *(float2*)(g_v + i0) = make_float2(c0, c1);
                *(float2*)(g_v + i1) = make_float2(c2, c3);
            } else if (MODE == 1) {
                const float2* vp0 = t0row
                    ? (const float2*)(g_wkv0 + (m0 >> 11) * (long)NDIM + n0)
                    : (const float2*)(g_v + i0);
                float2 v0 = *vp0;
                float2 v1 = *(const float2*)(g_v + i1);
                float r0 = 1.f / (1.f + __expf(-c0));
                float r1 = 1.f / (1.f + __expf(-c1));
                float r2 = 1.f / (1.f + __expf(-c2));
                float r3 = 1.f / (1.f + __expf(-c3));
                *(__half2*)(g_rv + i0) = __floats2half2_rn(r0 * v0.x, r1 * v0.y);
                *(__half2*)(g_rv + i1) = __floats2half2_rn(r2 * v1.x, r3 * v1.y);
            } else {
                *(float2*)(Cout + i0) = make_float2(c0, c1);
                *(float2*)(Cout + i1) = make_float2(c2, c3);
            }
        }
    }
}

extern "C" void kernel_launch(void* const* d_in, const int* in_sizes, int n_in,
                              void* d_out, int out_size) {
    (void)in_sizes; (void)n_in; (void)out_size;
    const float* x   = (const float*)d_in[0];
    const float* tf  = (const float*)d_in[1];
    const float* tmk = (const float*)d_in[2];
    const float* tmv = (const float*)d_in[3];
    const float* tmr = (const float*)d_in[4];
    const float* xxp = (const float*)d_in[5];
    const float* aa  = (const float*)d_in[6];
    const float* bb  = (const float*)d_in[7];
    const float* pp  = (const float*)d_in[8];
    const float* wk  = (const float*)d_in[9];
    const float* wv  = (const float*)d_in[10];
    const float* wr  = (const float*)d_in[11];
    const float* wo  = (const float*)d_in[12];
    float* out = (float*)d_out;

    static bool attr_done = false;
    if (!attr_done) {
        cudaFuncSetAttribute(gemm_f16<0>, cudaFuncAttributeMaxDynamicSharedMemorySize, DYN_SMEM);
        cudaFuncSetAttribute(gemm_f16<1>, cudaFuncAttributeMaxDynamicSharedMemorySize, DYN_SMEM);
        cudaFuncSetAttribute(gemm_f16<2>, cudaFuncAttributeMaxDynamicSharedMemorySize, DYN_SMEM);
        attr_done = true;
    }

    prep_w_kernel<<<(unsigned)(((long)NDIM * KDIM) / 1024), 256>>>(wv, wr, wo);
    prep_x_kernel<<<(unsigned)((MDIM * (long)KDIM) / 1024), 256>>>(x, tmv, tmr, xxp);
    t0_wkv_kernel<<<dim3(CDIM / 8, BDIM), 256>>>(x, tf, tmk, tmv, xxp, aa, bb, pp, wk, wv);

    dim3 grid((unsigned)(NDIM / BN), (unsigned)(MDIM / BM));   // (16, 64)
    gemm_f16<0><<<grid, NTHREADS, DYN_SMEM>>>(nullptr);        // g_v = xv @ Wv^T
    gemm_f16<1><<<grid, NTHREADS, DYN_SMEM>>>(nullptr);        // g_rv = sig(xr@Wr^T)*v
    gemm_f16<2><<<grid, NTHREADS, DYN_SMEM>>>(out);            // out = g_rv @ Wo^T
}

// round 16
// speedup vs baseline: 1.0898x; 1.0898x over previous
#include <cuda_runtime.h>
#include <cuda_fp16.h>
#include <cstdint>

// ---------------------------------------------------------------------------
// TimeMix collapses to: out = (sigmoid(xr @ Wr^T) * (xv @ Wv^T or wkv@t0)) @ Wo^T
// For t>0 padded state is zero so wkv == v; only 4 rows at t==0 need wkv.
// Engine: legacy mma.sync fp16 k16 (tcgen05 unusable: compute_103 target).
// R15: back to BK=64/3-stage (R13 base). 256 threads/CTA, 8 warps, warp tile
//      32x64 -> 16 warps/SM for TLP latency hiding (R15 profile: tensor 51%,
//      issue 20%, latency-bound at 8 warps/SM).
// ---------------------------------------------------------------------------

namespace {
constexpr int  BDIM = 4;
constexpr int  TDIM = 2048;
constexpr int  CDIM = 2048;
constexpr long MDIM = (long)BDIM * TDIM;   // 8192
constexpr int  KDIM = CDIM;
constexpr int  NDIM = CDIM;

constexpr int BM = 128, BN = 128, BK = 64;
constexpr int NTHREADS = 256;
constexpr int LSTR_H = 72;                          // padded row stride (halves)
constexpr int MAT_HALFS   = BM * LSTR_H;            // 9216
constexpr int MAT_BYTES   = MAT_HALFS * 2;          // 18432
constexpr int STAGE_HALFS = 2 * MAT_HALFS;
constexpr int STAGE_BYTES = STAGE_HALFS * 2;        // 36864
constexpr int NSTAGE = 3;
constexpr int DYN_SMEM = NSTAGE * STAGE_BYTES;      // 110592
constexpr int NKT = KDIM / BK;                      // 32
}

// Scratch (static device arrays — no cudaMalloc anywhere)
__device__ __half g_xv[MDIM * KDIM];
__device__ __half g_xr[MDIM * KDIM];
__device__ __half g_rv[MDIM * NDIM];
__device__ __half g_wv[(long)NDIM * KDIM];
__device__ __half g_wr[(long)NDIM * KDIM];
__device__ __half g_wo[(long)NDIM * KDIM];
__device__ float  g_v [MDIM * NDIM];

__device__ __forceinline__ void cp16(uint32_t s, const void* g) {
    asm volatile("cp.async.cg.shared.global [%0], [%1], 16;" :: "r"(s), "l"(g));
}

// ---- convert the three live weight matrices to fp16 (RN)
__global__ void prep_w_kernel(const float* __restrict__ wv,
                              const float* __restrict__ wr,
                              const float* __restrict__ wo) {
    long i = ((long)blockIdx.x * blockDim.x + threadIdx.x) * 4;
    float4 a = *(const float4*)(wv + i);
    float4 b = *(const float4*)(wr + i);
    float4 c = *(const float4*)(wo + i);
    __half2* pv = reinterpret_cast<__half2*>(g_wv + i);
    __half2* pr = reinterpret_cast<__half2*>(g_wr + i);
    __half2* po = reinterpret_cast<__half2*>(g_wo + i);
    pv[0] = __floats2half2_rn(a.x, a.y); pv[1] = __floats2half2_rn(a.z, a.w);
    pr[0] = __floats2half2_rn(b.x, b.y); pr[1] = __floats2half2_rn(b.z, b.w);
    po[0] = __floats2half2_rn(c.x, c.y); po[1] = __floats2half2_rn(c.z, c.w);
}

// ---- token-mix (fp32) + fp16 conversion for the two GEMM A-operands
__global__ void prep_x_kernel(const float* __restrict__ x,
                              const float* __restrict__ tmv,
                              const float* __restrict__ tmr,
                              const float* __restrict__ xxp) {
    long i = ((long)blockIdx.x * blockDim.x + threadIdx.x) * 4;
    int  c = (int)(i & (CDIM - 1));
    float4 xv = *(const float4*)(x   + i);
    float4 mv = *(const float4*)(tmv + c);
    float4 mr = *(const float4*)(tmr + c);
    float4 xc = *(const float4*)(xxp + c);
    float vx = xv.x * mv.x + (1.f - mv.x) * xc.x;
    float vy = xv.y * mv.y + (1.f - mv.y) * xc.y;
    float vz = xv.z * mv.z + (1.f - mv.z) * xc.z;
    float vw = xv.w * mv.w + (1.f - mv.w) * xc.w;
    float rx = xv.x * mr.x + (1.f - mr.x) * xc.x;
    float ry = xv.y * mr.y + (1.f - mr.y) * xc.y;
    float rz = xv.z * mr.z + (1.f - mr.z) * xc.z;
    float rw = xv.w * mr.w + (1.f - mr.w) * xc.w;
    __half2* pv = reinterpret_cast<__half2*>(g_xv + i);
    __half2* pr = reinterpret_cast<__half2*>(g_xr + i);
    pv[0] = __floats2half2_rn(vx, vy); pv[1] = __floats2half2_rn(vz, vw);
    pr[0] = __floats2half2_rn(rx, ry); pr[1] = __floats2half2_rn(rz, rw);
}

// ---- t==0 correction: full wkv for the 4 t=0 rows, overwrite g_v (fp32 dot).
__global__ void t0_fix_kernel(const float* __restrict__ x,
                              const float* __restrict__ tf,
                              const float* __restrict__ tmk,
                              const float* __restrict__ xxp,
                              const float* __restrict__ aa,
                              const float* __restrict__ bb,
                              const float* __restrict__ pp,
                              const float* __restrict__ wk) {
    const int b    = blockIdx.y;
    const int o    = blockIdx.x * 8 + (threadIdx.x >> 5);
    const int lane = threadIdx.x & 31;
    const float* xrow = x  + (long)b * TDIM * CDIM;
    const float* wrow = wk + (long)o * CDIM;
    float s = 0.f;
    for (int c = lane * 4; c < CDIM; c += 128) {
        float4 xc = *(const float4*)(xrow + c);
        float4 mk = *(const float4*)(tmk + c);
        float4 mx = *(const float4*)(xxp + c);
        float4 wr = *(const float4*)(wrow + c);
        s += (xc.x * mk.x + (1.f - mk.x) * mx.x) * wr.x;
        s += (xc.y * mk.y + (1.f - mk.y) * mx.y) * wr.y;
        s += (xc.z * mk.z + (1.f - mk.z) * mx.z) * wr.z;
        s += (xc.w * mk.w + (1.f - mk.w) * mx.w) * wr.w;
    }
    #pragma unroll
    for (int off = 16; off; off >>= 1) s += __shfl_xor_sync(0xffffffffu, s, off);
    if (lane == 0) {
        float ww = tf[o] + s;
        float p  = pp[o];
        float qq = fmaxf(p, ww);
        float e1 = expf(p  - qq);
        float e2 = expf(ww - qq);
        long idx = (long)b * TDIM * NDIM + o;
        float v  = g_v[idx];
        g_v[idx] = (e1 * aa[o] + e2 * v) / (e1 * bb[o] + e2);
    }
}

// ---- fp16 mma.sync GEMM:  C[M,N] = A[M,K] @ W[N,K]^T, CTA 128x128,
//      8 warps, warp tile 32x64, BK=64 (4 x k16 steps), 3-stage cp.async.
// MODE 0: g_v  = g_xv @ g_wv^T                      (fp32 out)
// MODE 1: g_rv = half( sigmoid(g_xr @ g_wr^T) * g_v )
// MODE 2: out  = g_rv @ g_wo^T                      (fp32 out)
template<int MODE>
__global__ void __launch_bounds__(NTHREADS, 2)
gemm_f16(float* __restrict__ Cout) {
    const __half* __restrict__ A = (MODE == 0) ? g_xv : (MODE == 1) ? g_xr : g_rv;
    const __half* __restrict__ W = (MODE == 0) ? g_wv : (MODE == 1) ? g_wr : g_wo;

    extern __shared__ __half smh[];   // [3 stages][A 128x72h | B 128x72h]

    const int tid  = threadIdx.x;
    const int lane = tid & 31;
    const int warp = tid >> 5;
    const int wm = warp & 3;          // 4 warps over M (32 rows each)
    const int wn = warp >> 2;         // 2 warps over N (64 cols each)
    const int g  = lane >> 2;
    const int t  = lane & 3;
    const long bm = (long)blockIdx.y * BM;
    const long bn = (long)blockIdx.x * BN;

    float acc[2][8][4];
    #pragma unroll
    for (int i = 0; i < 2; i++)
        #pragma unroll
        for (int j = 0; j < 8; j++)
            #pragma unroll
            for (int k = 0; k < 4; k++) acc[i][j][k] = 0.f;

    const uint32_t sbase = (uint32_t)__cvta_generic_to_shared(smh);

    // cp.async: per stage A = 128 rows x 8 chunks(16B) = 1024 -> 4/thread; B same.
    const int srow = tid >> 3;            // 0..31
    const int schk = (tid & 7) * 8;       // half offset of 16B chunk
    const __half* gA = A + (bm + srow) * (long)KDIM + schk;
    const __half* gB = W + (bn + srow) * (long)KDIM + schk;
    const uint32_t dOff = (uint32_t)(srow * LSTR_H + schk) * 2u;

    #define LOAD_STAGE(s, kt) do {                                               \
        uint32_t _a = sbase + (uint32_t)(s) * STAGE_BYTES + dOff;                \
        uint32_t _b = _a + (uint32_t)MAT_BYTES;                                  \
        int _k = (kt) * BK;                                                      \
        _Pragma("unroll")                                                        \
        for (int _i = 0; _i < 4; _i++) {                                         \
            cp16(_a + (uint32_t)(_i * 32 * LSTR_H * 2), gA + (long)(_i * 32) * KDIM + _k); \
            cp16(_b + (uint32_t)(_i * 32 * LSTR_H * 2), gB + (long)(_i * 32) * KDIM + _k); \
        }                                                                        \
        asm volatile("cp.async.commit_group;");                                  \
    } while (0)

    // Fragment load for one k16 step (packed half2 in u32)
    #define LOAD_FRAGS(fa, fb, As_, Bs_, ks) do {                                \
        _Pragma("unroll")                                                        \
        for (int _im = 0; _im < 2; _im++) {                                      \
            const __half* _p = (As_) + (wm * 32 + _im * 16 + g) * LSTR_H + (ks) * 16 + 2 * t; \
            (fa)[_im][0] = *(const uint32_t*)(_p);                               \
            (fa)[_im][1] = *(const uint32_t*)(_p + 8 * LSTR_H);                  \
            (fa)[_im][2] = *(const uint32_t*)(_p + 8);                           \
            (fa)[_im][3] = *(const uint32_t*)(_p + 8 * LSTR_H + 8);              \
        }                                                                        \
        _Pragma("unroll")                                                        \
        for (int _in = 0; _in < 8; _in++) {                                      \
            const __half* _p = (Bs_) + (wn * 64 + _in * 8 + g) * LSTR_H + (ks) * 16 + 2 * t; \
            (fb)[_in][0] = *(const uint32_t*)(_p);                               \
            (fb)[_in][1] = *(const uint32_t*)(_p + 8);                           \
        }                                                                        \
    } while (0)

    LOAD_STAGE(0, 0);
    LOAD_STAGE(1, 1);

    uint32_t a[2][4], b[8][2];

    for (int kt = 0; kt < NKT; ++kt) {
        asm volatile("cp.async.wait_group 1;" ::: "memory");
        __syncthreads();
        const __half* As_ = smh + (kt % NSTAGE) * STAGE_HALFS;
        const __half* Bs_ = As_ + MAT_HALFS;
        const int jt = kt + 2;
        if (jt < NKT) { LOAD_STAGE(jt % NSTAGE, jt); }
        else          { asm volatile("cp.async.commit_group;"); }
        #pragma unroll
        for (int ks = 0; ks < 4; ks++) {
            LOAD_FRAGS(a, b, As_, Bs_, ks);
            #pragma unroll
            for (int im = 0; im < 2; im++)
                #pragma unroll
                for (int in = 0; in < 8; in++)
                    asm volatile(
                        "mma.sync.aligned.m16n8k16.row.col.f32.f16.f16.f32 "
                        "{%0,%1,%2,%3}, {%4,%5,%6,%7}, {%8,%9}, {%0,%1,%2,%3};"
                        : "+f"(acc[im][in][0]), "+f"(acc[im][in][1]),
                          "+f"(acc[im][in][2]), "+f"(acc[im][in][3])
                        : "r"(a[im][0]), "r"(a[im][1]),
                          "r"(a[im][2]), "r"(a[im][3]),
                          "r"(b[in][0]), "r"(b[in][1]));
        }
    }
    #undef LOAD_STAGE
    #undef LOAD_FRAGS

    // Epilogue: c0,c1 = (row m0, cols n0,n0+1); c2,c3 = row m0+8.
    #pragma unroll
    for (int im = 0; im < 2; im++) {
        const long m0 = bm + wm * 32 + im * 16 + g;
        #pragma unroll
        for (int in = 0; in < 8; in++) {
            const long n0 = bn + wn * 64 + in * 8 + t * 2;
            const long i0 = m0 * NDIM + n0;
            const long i1 = i0 + 8L * NDIM;
            float c0 = acc[im][in][0], c1 = acc[im][in][1];
            float c2 = acc[im][in][2], c3 = acc[im][in][3];
            if (MODE == 0) {
                *(float2*)(g_v + i0) = make_float2(c0, c1);
                *(float2*)(g_v + i1) = make_float2(c2, c3);
            } else if (MODE == 1) {
                float2 v0 = *(const float2*)(g_v + i0);
                float2 v1 = *(const float2*)(g_v + i1);
                float r0 = 1.f / (1.f + __expf(-c0));
                float r1 = 1.f / (1.f + __expf(-c1));
                float r2 = 1.f / (1.f + __expf(-c2));
                float r3 = 1.f / (1.f + __expf(-c3));
                *(__half2*)(g_rv + i0) = __floats2half2_rn(r0 * v0.x, r1 * v0.y);
                *(__half2*)(g_rv + i1) = __floats2half2_rn(r2 * v1.x, r3 * v1.y);
            } else {
                *(float2*)(Cout + i0) = make_float2(c0, c1);
                *(float2*)(Cout + i1) = make_float2(c2, c3);
            }
        }
    }
}

extern "C" void kernel_launch(void* const* d_in, const int* in_sizes, int n_in,
                              void* d_out, int out_size) {
    (void)in_sizes; (void)n_in; (void)out_size;
    const float* x   = (const float*)d_in[0];
    const float* tf  = (const float*)d_in[1];
    const float* tmk = (const float*)d_in[2];
    const float* tmv = (const float*)d_in[3];
    const float* tmr = (const float*)d_in[4];
    const float* xxp = (const float*)d_in[5];
    const float* aa  = (const float*)d_in[6];
    const float* bb  = (const float*)d_in[7];
    const float* pp  = (const float*)d_in[8];
    const float* wk  = (const float*)d_in[9];
    const float* wv  = (const float*)d_in[10];
    const float* wr  = (const float*)d_in[11];
    const float* wo  = (const float*)d_in[12];
    float* out = (float*)d_out;

    static bool attr_done = false;
    if (!attr_done) {
        cudaFuncSetAttribute(gemm_f16<0>, cudaFuncAttributeMaxDynamicSharedMemorySize, DYN_SMEM);
        cudaFuncSetAttribute(gemm_f16<1>, cudaFuncAttributeMaxDynamicSharedMemorySize, DYN_SMEM);
        cudaFuncSetAttribute(gemm_f16<2>, cudaFuncAttributeMaxDynamicSharedMemorySize, DYN_SMEM);
        attr_done = true;
    }

    prep_w_kernel<<<(unsigned)(((long)NDIM * KDIM) / 1024), 256>>>(wv, wr, wo);
    prep_x_kernel<<<(unsigned)((MDIM * (long)KDIM) / 1024), 256>>>(x, tmv, tmr, xxp);

    dim3 grid((unsigned)(NDIM / BN), (unsigned)(MDIM / BM));   // (16, 64)
    gemm_f16<0><<<grid, NTHREADS, DYN_SMEM>>>(nullptr);        // g_v = xv @ Wv^T
    t0_fix_kernel<<<dim3(CDIM / 8, BDIM), 256>>>(x, tf, tmk, xxp, aa, bb, pp, wk);
    gemm_f16<1><<<grid, NTHREADS, DYN_SMEM>>>(nullptr);        // g_rv = sig(xr@Wr^T)*g_v
    gemm_f16<2><<<grid, NTHREADS, DYN_SMEM>>>(out);            // out = g_rv @ Wo^T
}